// round 6
// baseline (speedup 1.0000x reference)
#include <cuda_runtime.h>
#include <cuda_bf16.h>
#include <stdint.h>

// GCN_57501022159512: 2-layer GCN, N=100000 nodes, E=1600000 edges, 64 -> 128 -> 128.
// h1 = relu(gcnconv(x, W1, b1)); t = batchnorm(h1); out = relu(gcnconv(t, W2, b2))
//
// R6: replace atomic scatter with CSR gather (counting sort by destination,
// built once, reused by both layers). Gather fuses self-loop + bias + ReLU
// (+ BN stats for layer 1), eliminating both finalize passes and all zeroing
// of the big buffers. LTS traffic per layer: 820MB read + 51MB write
// (was 820MB read + 820MB atomic RMW + finalize passes).

#define NNODES 100000
#define NEDGES 1600000
#define FIN    64
#define FHID   128
#define BN_EPS 1e-5f

// ---------------- scratch (device globals; no allocs allowed) ----------------
__device__ float g_h1[NNODES * FHID];    // x @ W1
__device__ float g_t [NNODES * FHID];    // relu/bn input (gather1 output)
__device__ float g_h2[NNODES * FHID];    // bn(t) @ W2
__device__ float g_dinv[NNODES];
__device__ int   g_deg [NNODES];
__device__ float g_stats[2 * FHID];      // sum,sumsq -> then scale,shift
__device__ int   g_eidx[2 * NEDGES];     // decoded int32 edge index [row | col]
__device__ int   g_off [NNODES + 1];     // CSR offsets (by destination col)
__device__ int   g_cursor[NNODES];       // placement cursors
__device__ int2  g_csr[NEDGES];          // (src row, norm bits) sorted by dest
__device__ int   g_is64;

// ---------------- small setup kernels ----------------

__global__ void k_zero() {
    const int idx = blockIdx.x * blockDim.x + threadIdx.x;
    const int stride = gridDim.x * blockDim.x;
    for (int j = idx; j < NNODES; j += stride) g_deg[j] = 0;
    if (idx < 2 * FHID) g_stats[idx] = 0.f;
}

// Detect whether the edge_index buffer is int64 or int32.
__global__ void k_detect(const int* __restrict__ w) {
    __shared__ int bad;
    if (threadIdx.x == 0) bad = 0;
    __syncthreads();
    for (int j = threadIdx.x; j < 1024; j += blockDim.x) {
        const int lo = w[2 * j], hi = w[2 * j + 1];
        if (hi != 0 || lo < 0 || lo >= NNODES) bad = 1;
    }
    __syncthreads();
    if (threadIdx.x == 0) g_is64 = (bad == 0) ? 1 : 0;
}

// Decode edge indices into int32 scratch (clamped) + degree count on col.
__global__ void k_decode(const void* __restrict__ ei) {
    const int idx = blockIdx.x * blockDim.x + threadIdx.x;
    const int stride = gridDim.x * blockDim.x;
    const bool is64 = (g_is64 != 0);
    const long long* e64 = (const long long*)ei;
    const int*       e32 = (const int*)ei;
    for (int e = idx; e < 2 * NEDGES; e += stride) {
        int v = is64 ? (int)e64[e] : e32[e];
        v = min(max(v, 0), NNODES - 1);
        g_eidx[e] = v;
        if (e >= NEDGES) atomicAdd(&g_deg[v], 1);   // col half -> degree
    }
}

__global__ void k_dinv() {
    const int idx = blockIdx.x * blockDim.x + threadIdx.x;
    const int stride = gridDim.x * blockDim.x;
    for (int n = idx; n < NNODES; n += stride)
        g_dinv[n] = rsqrtf((float)(g_deg[n] + 1));
}

// Exclusive prefix sum of g_deg -> g_off, g_cursor. Single block, 1024 threads.
__global__ void k_scan() {
    __shared__ int ssum[1024];
    const int t = threadIdx.x;
    const int per = (NNODES + 1023) / 1024;          // 98
    const int beg = t * per;
    const int end = min(beg + per, NNODES);
    int s = 0;
    for (int i = beg; i < end; i++) s += g_deg[i];
    ssum[t] = s;
    __syncthreads();
    // Hillis-Steele inclusive scan
    for (int d = 1; d < 1024; d <<= 1) {
        int v = (t >= d) ? ssum[t - d] : 0;
        __syncthreads();
        ssum[t] += v;
        __syncthreads();
    }
    int run = (t == 0) ? 0 : ssum[t - 1];
    for (int i = beg; i < end; i++) {
        g_off[i] = run;
        g_cursor[i] = run;
        run += g_deg[i];
    }
    if (t == 0) g_off[NNODES] = ssum[1023];
}

// Counting sort: place (row, norm) records into destination-sorted CSR array.
__global__ void k_fillcsr() {
    const int idx = blockIdx.x * blockDim.x + threadIdx.x;
    const int stride = gridDim.x * blockDim.x;
    for (int e = idx; e < NEDGES; e += stride) {
        const int r = g_eidx[e];
        const int c = g_eidx[NEDGES + e];
        const int pos = atomicAdd(&g_cursor[c], 1);
        const float nm = g_dinv[r] * g_dinv[c];
        g_csr[pos] = make_int2(r, __float_as_int(nm));
    }
}

// ---------------- GEMMs ----------------

// h1 = x @ W1.  128 threads/block; thread f keeps W1[:,f] (64 vals) in regs.
__global__ void k_gemm1(const float* __restrict__ x, const float* __restrict__ W1) {
    __shared__ float sx[4][FIN];
    const int f = threadIdx.x;
    float w[FIN];
#pragma unroll
    for (int k = 0; k < FIN; k++) w[k] = W1[k * FHID + f];

    for (int base = blockIdx.x * 4; base < NNODES; base += gridDim.x * 4) {
        for (int i = threadIdx.x; i < 4 * FIN; i += FHID)
            sx[i >> 6][i & 63] = x[(size_t)base * FIN + i];
        __syncthreads();
#pragma unroll
        for (int j = 0; j < 4; j++) {
            float acc = 0.f;
#pragma unroll
            for (int k = 0; k < FIN; k++) acc = fmaf(sx[j][k], w[k], acc);
            g_h1[(size_t)(base + j) * FHID + f] = acc;
        }
        __syncthreads();
    }
}

// h2 = bn(t) @ W2.  thread f keeps W2[:,f] (128 vals) in regs; BN applied on row load.
__global__ void __launch_bounds__(FHID, 3) k_gemm2(const float* __restrict__ W2) {
    __shared__ float su[2][FHID];
    const int f = threadIdx.x;
    float w[FHID];
#pragma unroll
    for (int k = 0; k < FHID; k++) w[k] = W2[k * FHID + f];
    const float scale = g_stats[f];
    const float shift = g_stats[FHID + f];

    for (int base = blockIdx.x * 2; base < NNODES; base += gridDim.x * 2) {
        su[0][f] = fmaf(g_t[(size_t)base * FHID + f], scale, shift);
        su[1][f] = fmaf(g_t[(size_t)(base + 1) * FHID + f], scale, shift);
        __syncthreads();
#pragma unroll
        for (int j = 0; j < 2; j++) {
            float acc = 0.f;
#pragma unroll
            for (int k = 0; k < FHID; k++) acc = fmaf(su[j][k], w[k], acc);
            g_h2[(size_t)(base + j) * FHID + f] = acc;
        }
        __syncthreads();
    }
}

// ---------------- gathers (warp per destination node) ----------------

// t[c] = relu( sum_{e->c} h1[r]*norm + h1[c]*dinv[c]^2 + b1 ); BN partial sums.
__global__ void k_gather1(const float* __restrict__ b1) {
    const int lane = threadIdx.x & 31;                 // feature quad
    const int warp = (blockIdx.x * blockDim.x + threadIdx.x) >> 5;
    const int nwarps = (gridDim.x * blockDim.x) >> 5;
    const float4 bf = reinterpret_cast<const float4*>(b1)[lane];
    const float4* h4 = reinterpret_cast<const float4*>(g_h1);
    float4* t4 = reinterpret_cast<float4*>(g_t);
    float4 s  = make_float4(0.f, 0.f, 0.f, 0.f);
    float4 ss = make_float4(0.f, 0.f, 0.f, 0.f);

    for (int c = warp; c < NNODES; c += nwarps) {
        const int beg = g_off[c], end = g_off[c + 1];
        const float dc = g_dinv[c];
        const float d2 = dc * dc;
        float4 h = h4[(size_t)c * 32 + lane];
        float4 acc = make_float4(h.x * d2, h.y * d2, h.z * d2, h.w * d2);
        for (int i = beg; i < end; i++) {
            const int2 en = g_csr[i];
            const float nm = __int_as_float(en.y);
            const float4 v = h4[(size_t)en.x * 32 + lane];
            acc.x = fmaf(v.x, nm, acc.x);
            acc.y = fmaf(v.y, nm, acc.y);
            acc.z = fmaf(v.z, nm, acc.z);
            acc.w = fmaf(v.w, nm, acc.w);
        }
        acc.x = fmaxf(acc.x + bf.x, 0.f);
        acc.y = fmaxf(acc.y + bf.y, 0.f);
        acc.z = fmaxf(acc.z + bf.z, 0.f);
        acc.w = fmaxf(acc.w + bf.w, 0.f);
        t4[(size_t)c * 32 + lane] = acc;
        s.x += acc.x; s.y += acc.y; s.z += acc.z; s.w += acc.w;
        ss.x += acc.x * acc.x; ss.y += acc.y * acc.y;
        ss.z += acc.z * acc.z; ss.w += acc.w * acc.w;
    }
    float* st = &g_stats[4 * lane];
    atomicAdd(st + 0, s.x); atomicAdd(st + 1, s.y);
    atomicAdd(st + 2, s.z); atomicAdd(st + 3, s.w);
    st = &g_stats[FHID + 4 * lane];
    atomicAdd(st + 0, ss.x); atomicAdd(st + 1, ss.y);
    atomicAdd(st + 2, ss.z); atomicAdd(st + 3, ss.w);
}

// out[c] = relu( sum_{e->c} h2[r]*norm + h2[c]*dinv[c]^2 + b2 )
__global__ void k_gather2(float* __restrict__ out, const float* __restrict__ b2) {
    const int lane = threadIdx.x & 31;
    const int warp = (blockIdx.x * blockDim.x + threadIdx.x) >> 5;
    const int nwarps = (gridDim.x * blockDim.x) >> 5;
    const float4 bf = reinterpret_cast<const float4*>(b2)[lane];
    const float4* h4 = reinterpret_cast<const float4*>(g_h2);
    float4* o4 = reinterpret_cast<float4*>(out);

    for (int c = warp; c < NNODES; c += nwarps) {
        const int beg = g_off[c], end = g_off[c + 1];
        const float dc = g_dinv[c];
        const float d2 = dc * dc;
        float4 h = h4[(size_t)c * 32 + lane];
        float4 acc = make_float4(h.x * d2, h.y * d2, h.z * d2, h.w * d2);
        for (int i = beg; i < end; i++) {
            const int2 en = g_csr[i];
            const float nm = __int_as_float(en.y);
            const float4 v = h4[(size_t)en.x * 32 + lane];
            acc.x = fmaf(v.x, nm, acc.x);
            acc.y = fmaf(v.y, nm, acc.y);
            acc.z = fmaf(v.z, nm, acc.z);
            acc.w = fmaf(v.w, nm, acc.w);
        }
        acc.x = fmaxf(acc.x + bf.x, 0.f);
        acc.y = fmaxf(acc.y + bf.y, 0.f);
        acc.z = fmaxf(acc.z + bf.z, 0.f);
        acc.w = fmaxf(acc.w + bf.w, 0.f);
        o4[(size_t)c * 32 + lane] = acc;
    }
}

// fold BN into per-feature scale/shift
__global__ void k_bnfold(const float* __restrict__ gamma, const float* __restrict__ beta) {
    const int f = threadIdx.x;
    const float inv_n = 1.0f / (float)NNODES;
    const float mean = g_stats[f] * inv_n;
    const float var  = g_stats[FHID + f] * inv_n - mean * mean;
    const float rstd = rsqrtf(var + BN_EPS);
    const float scale = gamma[f] * rstd;
    g_stats[f]        = scale;
    g_stats[FHID + f] = beta[f] - mean * scale;
}

// ---------------- launch ----------------
extern "C" void kernel_launch(void* const* d_in, const int* in_sizes, int n_in,
                              void* d_out, int out_size) {
    const float* x     = (const float*)d_in[0];
    const void*  ei    = d_in[1];                 // [2, E], int32 OR int64 (detected)
    const float* W1    = (const float*)d_in[2];
    const float* b1    = (const float*)d_in[3];
    const float* gamma = (const float*)d_in[4];
    const float* beta  = (const float*)d_in[5];
    const float* W2    = (const float*)d_in[6];
    const float* b2    = (const float*)d_in[7];
    float* out = (float*)d_out;

    k_zero<<<512, 256>>>();
    k_detect<<<1, 256>>>((const int*)ei);
    k_decode<<<2048, 256>>>(ei);
    k_scan<<<1, 1024>>>();
    k_dinv<<<512, 256>>>();
    k_fillcsr<<<2048, 256>>>();

    k_gemm1<<<888, FHID>>>(x, W1);
    k_gather1<<<1184, 256>>>(b1);
    k_bnfold<<<1, FHID>>>(gamma, beta);

    k_gemm2<<<444, FHID>>>(W2);
    k_gather2<<<1184, 256>>>(out, b2);
}

// round 7
// speedup vs baseline: 1.2564x; 1.2564x over previous
#include <cuda_runtime.h>
#include <cuda_bf16.h>
#include <stdint.h>

// GCN_57501022159512: 2-layer GCN, N=100000 nodes, E=1600000 edges, 64 -> 128 -> 128.
// h1 = relu(gcnconv(x, W1, b1)); t = batchnorm(h1); out = relu(gcnconv(t, W2, b2))
//
// R7: fix the R6 regression — the single-block k_scan (161us, 1 SM busy) is
// replaced by a two-stage chip-wide scan (100 blocks x 1000 nodes), with
// dinv computation fused into stage C. CSR gather path otherwise unchanged.

#define NNODES 100000
#define NEDGES 1600000
#define FIN    64
#define FHID   128
#define BN_EPS 1e-5f

#define NB_SCAN 100
#define NODES_PER_BLK 1000   // NNODES / NB_SCAN, exact

// ---------------- scratch (device globals; no allocs allowed) ----------------
__device__ float g_h1[NNODES * FHID];    // x @ W1
__device__ float g_t [NNODES * FHID];    // relu/bn input (gather1 output)
__device__ float g_h2[NNODES * FHID];    // bn(t) @ W2
__device__ float g_dinv[NNODES];
__device__ int   g_deg [NNODES];
__device__ float g_stats[2 * FHID];      // sum,sumsq -> then scale,shift
__device__ int   g_eidx[2 * NEDGES];     // decoded int32 edge index [row | col]
__device__ int   g_off [NNODES + 1];     // CSR offsets (by destination col)
__device__ int   g_cursor[NNODES];       // placement cursors
__device__ int2  g_csr[NEDGES];          // (src row, norm bits) sorted by dest
__device__ int   g_bsum[NB_SCAN];        // per-block degree sums
__device__ int   g_is64;

// ---------------- small setup kernels ----------------

__global__ void k_zero() {
    const int idx = blockIdx.x * blockDim.x + threadIdx.x;
    const int stride = gridDim.x * blockDim.x;
    for (int j = idx; j < NNODES; j += stride) g_deg[j] = 0;
    if (idx < 2 * FHID) g_stats[idx] = 0.f;
}

// Detect whether the edge_index buffer is int64 or int32.
__global__ void k_detect(const int* __restrict__ w) {
    __shared__ int bad;
    if (threadIdx.x == 0) bad = 0;
    __syncthreads();
    for (int j = threadIdx.x; j < 1024; j += blockDim.x) {
        const int lo = w[2 * j], hi = w[2 * j + 1];
        if (hi != 0 || lo < 0 || lo >= NNODES) bad = 1;
    }
    __syncthreads();
    if (threadIdx.x == 0) g_is64 = (bad == 0) ? 1 : 0;
}

// Decode edge indices into int32 scratch (clamped) + degree count on col.
__global__ void k_decode(const void* __restrict__ ei) {
    const int idx = blockIdx.x * blockDim.x + threadIdx.x;
    const int stride = gridDim.x * blockDim.x;
    const bool is64 = (g_is64 != 0);
    const long long* e64 = (const long long*)ei;
    const int*       e32 = (const int*)ei;
    for (int e = idx; e < 2 * NEDGES; e += stride) {
        int v = is64 ? (int)e64[e] : e32[e];
        v = min(max(v, 0), NNODES - 1);
        g_eidx[e] = v;
        if (e >= NEDGES) atomicAdd(&g_deg[v], 1);   // col half -> degree
    }
}

// Stage A: per-block degree sums. Block b covers nodes [b*1000, (b+1)*1000).
__global__ void k_scanA() {
    __shared__ int red[256];
    const int b = blockIdx.x;
    const int t = threadIdx.x;
    const int beg = b * NODES_PER_BLK;
    int s = 0;
    for (int i = t; i < NODES_PER_BLK; i += 256) s += g_deg[beg + i];
    red[t] = s;
    __syncthreads();
    for (int d = 128; d > 0; d >>= 1) {
        if (t < d) red[t] += red[t + d];
        __syncthreads();
    }
    if (t == 0) g_bsum[b] = red[0];
}

// Stage C: block b computes its base (sum of preceding block sums), scans its
// 1000 nodes, writes g_off / g_cursor, and computes g_dinv (fused).
__global__ void k_scanC() {
    __shared__ int red[256];
    __shared__ int partial[256];
    __shared__ int s_base;
    const int b = blockIdx.x;
    const int t = threadIdx.x;
    const int beg = b * NODES_PER_BLK;

    // base = sum of g_bsum[0..b)
    int s = (t < b) ? g_bsum[t] : 0;
    red[t] = s;
    __syncthreads();
    for (int d = 128; d > 0; d >>= 1) {
        if (t < d) red[t] += red[t + d];
        __syncthreads();
    }
    if (t == 0) s_base = red[0];
    __syncthreads();

    // per-thread chunk of 4 consecutive nodes (256*4 >= 1000)
    const int cbeg = t * 4;
    int csum = 0;
    int dloc[4];
#pragma unroll
    for (int j = 0; j < 4; j++) {
        const int i = cbeg + j;
        dloc[j] = (i < NODES_PER_BLK) ? g_deg[beg + i] : 0;
        csum += dloc[j];
    }
    partial[t] = csum;
    __syncthreads();
    // Hillis-Steele inclusive scan of 256 partials
    for (int d = 1; d < 256; d <<= 1) {
        int v = (t >= d) ? partial[t - d] : 0;
        __syncthreads();
        partial[t] += v;
        __syncthreads();
    }
    int run = s_base + ((t == 0) ? 0 : partial[t - 1]);
#pragma unroll
    for (int j = 0; j < 4; j++) {
        const int i = cbeg + j;
        if (i < NODES_PER_BLK) {
            g_off[beg + i] = run;
            g_cursor[beg + i] = run;
            g_dinv[beg + i] = rsqrtf((float)(dloc[j] + 1));
            run += dloc[j];
        }
    }
    if (b == NB_SCAN - 1 && t == 255) g_off[NNODES] = run;
}

// Counting sort: place (row, norm) records into destination-sorted CSR array.
__global__ void k_fillcsr() {
    const int idx = blockIdx.x * blockDim.x + threadIdx.x;
    const int stride = gridDim.x * blockDim.x;
    for (int e = idx; e < NEDGES; e += stride) {
        const int r = g_eidx[e];
        const int c = g_eidx[NEDGES + e];
        const int pos = atomicAdd(&g_cursor[c], 1);
        const float nm = g_dinv[r] * g_dinv[c];
        g_csr[pos] = make_int2(r, __float_as_int(nm));
    }
}

// ---------------- GEMMs ----------------

// h1 = x @ W1.  128 threads/block; thread f keeps W1[:,f] (64 vals) in regs.
__global__ void k_gemm1(const float* __restrict__ x, const float* __restrict__ W1) {
    __shared__ float sx[4][FIN];
    const int f = threadIdx.x;
    float w[FIN];
#pragma unroll
    for (int k = 0; k < FIN; k++) w[k] = W1[k * FHID + f];

    for (int base = blockIdx.x * 4; base < NNODES; base += gridDim.x * 4) {
        for (int i = threadIdx.x; i < 4 * FIN; i += FHID)
            sx[i >> 6][i & 63] = x[(size_t)base * FIN + i];
        __syncthreads();
#pragma unroll
        for (int j = 0; j < 4; j++) {
            float acc = 0.f;
#pragma unroll
            for (int k = 0; k < FIN; k++) acc = fmaf(sx[j][k], w[k], acc);
            g_h1[(size_t)(base + j) * FHID + f] = acc;
        }
        __syncthreads();
    }
}

// h2 = bn(t) @ W2.  thread f keeps W2[:,f] (128 vals) in regs; BN applied on row load.
__global__ void __launch_bounds__(FHID, 3) k_gemm2(const float* __restrict__ W2) {
    __shared__ float su[2][FHID];
    const int f = threadIdx.x;
    float w[FHID];
#pragma unroll
    for (int k = 0; k < FHID; k++) w[k] = W2[k * FHID + f];
    const float scale = g_stats[f];
    const float shift = g_stats[FHID + f];

    for (int base = blockIdx.x * 2; base < NNODES; base += gridDim.x * 2) {
        su[0][f] = fmaf(g_t[(size_t)base * FHID + f], scale, shift);
        su[1][f] = fmaf(g_t[(size_t)(base + 1) * FHID + f], scale, shift);
        __syncthreads();
#pragma unroll
        for (int j = 0; j < 2; j++) {
            float acc = 0.f;
#pragma unroll
            for (int k = 0; k < FHID; k++) acc = fmaf(su[j][k], w[k], acc);
            g_h2[(size_t)(base + j) * FHID + f] = acc;
        }
        __syncthreads();
    }
}

// ---------------- gathers (warp per destination node) ----------------

// t[c] = relu( sum_{e->c} h1[r]*norm + h1[c]*dinv[c]^2 + b1 ); BN partial sums.
__global__ void k_gather1(const float* __restrict__ b1) {
    const int lane = threadIdx.x & 31;                 // feature quad
    const int warp = (blockIdx.x * blockDim.x + threadIdx.x) >> 5;
    const int nwarps = (gridDim.x * blockDim.x) >> 5;
    const float4 bf = reinterpret_cast<const float4*>(b1)[lane];
    const float4* h4 = reinterpret_cast<const float4*>(g_h1);
    float4* t4 = reinterpret_cast<float4*>(g_t);
    float4 s  = make_float4(0.f, 0.f, 0.f, 0.f);
    float4 ss = make_float4(0.f, 0.f, 0.f, 0.f);

    for (int c = warp; c < NNODES; c += nwarps) {
        const int beg = g_off[c], end = g_off[c + 1];
        const float dc = g_dinv[c];
        const float d2 = dc * dc;
        float4 h = h4[(size_t)c * 32 + lane];
        float4 acc = make_float4(h.x * d2, h.y * d2, h.z * d2, h.w * d2);
        for (int i = beg; i < end; i++) {
            const int2 en = g_csr[i];
            const float nm = __int_as_float(en.y);
            const float4 v = h4[(size_t)en.x * 32 + lane];
            acc.x = fmaf(v.x, nm, acc.x);
            acc.y = fmaf(v.y, nm, acc.y);
            acc.z = fmaf(v.z, nm, acc.z);
            acc.w = fmaf(v.w, nm, acc.w);
        }
        acc.x = fmaxf(acc.x + bf.x, 0.f);
        acc.y = fmaxf(acc.y + bf.y, 0.f);
        acc.z = fmaxf(acc.z + bf.z, 0.f);
        acc.w = fmaxf(acc.w + bf.w, 0.f);
        t4[(size_t)c * 32 + lane] = acc;
        s.x += acc.x; s.y += acc.y; s.z += acc.z; s.w += acc.w;
        ss.x += acc.x * acc.x; ss.y += acc.y * acc.y;
        ss.z += acc.z * acc.z; ss.w += acc.w * acc.w;
    }
    float* st = &g_stats[4 * lane];
    atomicAdd(st + 0, s.x); atomicAdd(st + 1, s.y);
    atomicAdd(st + 2, s.z); atomicAdd(st + 3, s.w);
    st = &g_stats[FHID + 4 * lane];
    atomicAdd(st + 0, ss.x); atomicAdd(st + 1, ss.y);
    atomicAdd(st + 2, ss.z); atomicAdd(st + 3, ss.w);
}

// out[c] = relu( sum_{e->c} h2[r]*norm + h2[c]*dinv[c]^2 + b2 )
__global__ void k_gather2(float* __restrict__ out, const float* __restrict__ b2) {
    const int lane = threadIdx.x & 31;
    const int warp = (blockIdx.x * blockDim.x + threadIdx.x) >> 5;
    const int nwarps = (gridDim.x * blockDim.x) >> 5;
    const float4 bf = reinterpret_cast<const float4*>(b2)[lane];
    const float4* h4 = reinterpret_cast<const float4*>(g_h2);
    float4* o4 = reinterpret_cast<float4*>(out);

    for (int c = warp; c < NNODES; c += nwarps) {
        const int beg = g_off[c], end = g_off[c + 1];
        const float dc = g_dinv[c];
        const float d2 = dc * dc;
        float4 h = h4[(size_t)c * 32 + lane];
        float4 acc = make_float4(h.x * d2, h.y * d2, h.z * d2, h.w * d2);
        for (int i = beg; i < end; i++) {
            const int2 en = g_csr[i];
            const float nm = __int_as_float(en.y);
            const float4 v = h4[(size_t)en.x * 32 + lane];
            acc.x = fmaf(v.x, nm, acc.x);
            acc.y = fmaf(v.y, nm, acc.y);
            acc.z = fmaf(v.z, nm, acc.z);
            acc.w = fmaf(v.w, nm, acc.w);
        }
        acc.x = fmaxf(acc.x + bf.x, 0.f);
        acc.y = fmaxf(acc.y + bf.y, 0.f);
        acc.z = fmaxf(acc.z + bf.z, 0.f);
        acc.w = fmaxf(acc.w + bf.w, 0.f);
        o4[(size_t)c * 32 + lane] = acc;
    }
}

// fold BN into per-feature scale/shift
__global__ void k_bnfold(const float* __restrict__ gamma, const float* __restrict__ beta) {
    const int f = threadIdx.x;
    const float inv_n = 1.0f / (float)NNODES;
    const float mean = g_stats[f] * inv_n;
    const float var  = g_stats[FHID + f] * inv_n - mean * mean;
    const float rstd = rsqrtf(var + BN_EPS);
    const float scale = gamma[f] * rstd;
    g_stats[f]        = scale;
    g_stats[FHID + f] = beta[f] - mean * scale;
}

// ---------------- launch ----------------
extern "C" void kernel_launch(void* const* d_in, const int* in_sizes, int n_in,
                              void* d_out, int out_size) {
    const float* x     = (const float*)d_in[0];
    const void*  ei    = d_in[1];                 // [2, E], int32 OR int64 (detected)
    const float* W1    = (const float*)d_in[2];
    const float* b1    = (const float*)d_in[3];
    const float* gamma = (const float*)d_in[4];
    const float* beta  = (const float*)d_in[5];
    const float* W2    = (const float*)d_in[6];
    const float* b2    = (const float*)d_in[7];
    float* out = (float*)d_out;

    k_zero<<<512, 256>>>();
    k_detect<<<1, 256>>>((const int*)ei);
    k_decode<<<2048, 256>>>(ei);
    k_scanA<<<NB_SCAN, 256>>>();
    k_scanC<<<NB_SCAN, 256>>>();
    k_fillcsr<<<2048, 256>>>();

    k_gemm1<<<888, FHID>>>(x, W1);
    k_gather1<<<1184, 256>>>(b1);
    k_bnfold<<<1, FHID>>>(gamma, beta);

    k_gemm2<<<444, FHID>>>(W2);
    k_gather2<<<1184, 256>>>(out, b2);
}